// round 16
// baseline (speedup 1.0000x reference)
#include <cuda_runtime.h>
#include <cstdint>

// ---------------- problem constants ----------------
#define NN 16
#define CC 64
#define HW 3136       // 56*56
#define WID 56
#define GRID 444      // 148 SMs x 3 blocks
#define NT 224        // threads per block
#define NW 7          // warps per block

// ---------------- device scratch ----------------
__device__ float g_maxabs_x, g_maxw1, g_maxw2, g_max_r1, g_max_r2;
__device__ float g_partX[GRID];
__device__ float g_partW[64];
__device__ unsigned g_qxp[NN*16*HW];     // packed int8 qx
__device__ unsigned g_q1p[NN*16*HW];     // packed uint8 q1
__device__ float    g_t1 [NN*CC*HW];     // bn1 output (pre-relu), fp32
__device__ unsigned g_qw1p[9216];        // packed weights [c4][pos][o]
__device__ unsigned g_qw2p[9216];
__device__ int g_wsum1[4608], g_wsum2[4608];
__device__ int g_stats1[9*512], g_stats2[9*512];
__device__ unsigned g_ctr[4];            // work-steal counters: qs1, conv1, qs2, conv2
__device__ unsigned g_bar, g_gen;        // grid barrier (generation-based, no reset needed)

__device__ __forceinline__ void atomicMaxF(float* a, float v) {
    atomicMax((int*)a, __float_as_int(v));
}
__device__ __forceinline__ float warpMaxPos(float v) {
    return __uint_as_float(__reduce_max_sync(0xffffffffu, __float_as_uint(v)));
}

__device__ __forceinline__ void gridBarrier() {
    __syncthreads();
    if (threadIdx.x == 0) {
        __threadfence();
        unsigned gen = *(volatile unsigned*)&g_gen;
        if (atomicAdd(&g_bar, 1u) == GRID - 1u) {
            g_bar = 0;
            __threadfence();
            atomicAdd(&g_gen, 1u);
        } else {
            while (*(volatile unsigned*)&g_gen == gen) __nanosleep(64);
        }
        __threadfence();
    }
    __syncthreads();
}

// int8 tensor-core mma: D(16x8,s32) += A(16x32) * B(32x8)
template<int PASS>
__device__ __forceinline__ void MMA8(int* c, unsigned a0, unsigned a1, unsigned a2, unsigned a3,
                                     unsigned b0, unsigned b1) {
    if (PASS == 1)
        asm volatile(
            "mma.sync.aligned.m16n8k32.row.col.s32.s8.s8.s32 "
            "{%0,%1,%2,%3},{%4,%5,%6,%7},{%8,%9},{%0,%1,%2,%3};"
            : "+r"(c[0]), "+r"(c[1]), "+r"(c[2]), "+r"(c[3])
            : "r"(a0), "r"(a1), "r"(a2), "r"(a3), "r"(b0), "r"(b1));
    else
        asm volatile(
            "mma.sync.aligned.m16n8k32.row.col.s32.u8.s8.s32 "
            "{%0,%1,%2,%3},{%4,%5,%6,%7},{%8,%9},{%0,%1,%2,%3};"
            : "+r"(c[0]), "+r"(c[1]), "+r"(c[2]), "+r"(c[3])
            : "r"(a0), "r"(a1), "r"(a2), "r"(a3), "r"(b0), "r"(b1));
}

// ---------------- qs phase: quantize + bit stats over 512 tiles (work-steal) ----
template<int PASS>
__device__ __forceinline__ void qsPhase(const float* __restrict__ src, float sinv,
                                        unsigned* scCor, unsigned* ws, int* sTile) {
    unsigned* qp = (PASS == 1) ? g_qxp : g_q1p;
    int* stats = (PASS == 1) ? g_stats1 : g_stats2;
    unsigned* ctr = &g_ctr[(PASS == 1) ? 0 : 2];
    const unsigned N4 = 0x11111111u;
    int tid = threadIdx.x;
    int wid = tid >> 5, lane = tid & 31;

    for (;;) {
        __syncthreads();
        if (tid == 0) *sTile = (int)atomicAdd(ctr, 1u);
        if (tid < 128) scCor[tid] = 0;
        __syncthreads();
        int tile = *sTile;
        if (tile >= 512) break;
        int n = tile >> 5, rem = tile & 31;
        int c4 = rem >> 1, half = rem & 1;
        const float4* s0 = (const float4*)(src + (size_t)(n*CC + c4*4)*HW);
        uint4* dst = (uint4*)(qp + (size_t)(n*16 + c4)*HW);

        auto qByte = [&](float v) -> unsigned {
            int q;
            if (PASS == 1) { q = __float2int_rn(v * sinv); q = ::max(-127, ::min(127, q)); }
            else           { q = __float2int_rn(fmaxf(v, 0.f) * sinv); q = ::min(255, q); }
            return (unsigned)q & 0xffu;
        };
        auto quantQuad = [&](int i, unsigned w[4]) {
            float4 f0 = s0[i], f1 = s0[784 + i], f2 = s0[1568 + i], f3 = s0[2352 + i];
            w[0] = qByte(f0.x) | (qByte(f1.x) << 8) | (qByte(f2.x) << 16) | (qByte(f3.x) << 24);
            w[1] = qByte(f0.y) | (qByte(f1.y) << 8) | (qByte(f2.y) << 16) | (qByte(f3.y) << 24);
            w[2] = qByte(f0.z) | (qByte(f1.z) << 8) | (qByte(f2.z) << 16) | (qByte(f3.z) << 24);
            w[3] = qByte(f0.w) | (qByte(f1.w) << 8) | (qByte(f2.w) << 16) | (qByte(f3.w) << 24);
        };

        unsigned accN[4] = {0,0,0,0};
        int ibase = half * 392;
        {
            int i0 = ibase + tid;             // tid < 224 < 392: always valid
            unsigned w[4];
            quantQuad(i0, w);
            dst[i0] = make_uint4(w[0], w[1], w[2], w[3]);
            #pragma unroll
            for (int k = 0; k < 4; k++)
                accN[k] += ((w[0]>>k)&N4) + ((w[1]>>k)&N4) + ((w[2]>>k)&N4) + ((w[3]>>k)&N4);
            if (tid + NT < 392) {
                int i1 = i0 + NT;
                quantQuad(i1, w);
                dst[i1] = make_uint4(w[0], w[1], w[2], w[3]);
                #pragma unroll
                for (int k = 0; k < 4; k++)
                    accN[k] += ((w[0]>>k)&N4) + ((w[1]>>k)&N4) + ((w[2]>>k)&N4) + ((w[3]>>k)&N4);
            }
        }

        // borders: warp 0 = row border, warp 1 = col 0, warp 2 = col 55
        unsigned aBN[4] = {0,0,0,0};
        if (wid == 0 && lane < 14) {
            int i = half ? 770 + lane : lane;
            unsigned w[4]; quantQuad(i, w);
            #pragma unroll
            for (int k = 0; k < 4; k++)
                aBN[k] += ((w[0]>>k)&N4) + ((w[1]>>k)&N4) + ((w[2]>>k)&N4) + ((w[3]>>k)&N4);
            if (lane == 0) {
                int corner = half ? 2 : 0;  unsigned u = w[0];
                #pragma unroll
                for (int l = 0; l < 32; l++) atomicAdd(&scCor[corner*32 + l], (u >> l) & 1u);
            }
            if (lane == 13) {
                int corner = half ? 3 : 1;  unsigned u = w[3];
                #pragma unroll
                for (int l = 0; l < 32; l++) atomicAdd(&scCor[corner*32 + l], (u >> l) & 1u);
            }
        } else if (wid == 1 && lane < 28) {
            int i = ibase + lane*14;
            unsigned w[4]; quantQuad(i, w);
            #pragma unroll
            for (int k = 0; k < 4; k++) aBN[k] += (w[0] >> k) & N4;
        } else if (wid == 2 && lane < 28) {
            int i = ibase + lane*14 + 13;
            unsigned w[4]; quantQuad(i, w);
            #pragma unroll
            for (int k = 0; k < 4; k++) aBN[k] += (w[3] >> k) & N4;
        }

        unsigned aLo[8], aHi[8], aB[8];
        #pragma unroll
        for (int k = 0; k < 4; k++) {
            unsigned lo = accN[k] & 0x0F0F0F0Fu;
            unsigned hi = (accN[k] >> 4) & 0x0F0F0F0Fu;
            aLo[k]   = __reduce_add_sync(0xffffffffu, lo & 0x00FF00FFu);
            aHi[k]   = __reduce_add_sync(0xffffffffu, (lo >> 8) & 0x00FF00FFu);
            aLo[k+4] = __reduce_add_sync(0xffffffffu, hi & 0x00FF00FFu);
            aHi[k+4] = __reduce_add_sync(0xffffffffu, (hi >> 8) & 0x00FF00FFu);
            aB[k]    = __reduce_add_sync(0xffffffffu, aBN[k] & 0x0F0F0F0Fu);
            aB[k+4]  = __reduce_add_sync(0xffffffffu, (aBN[k] >> 4) & 0x0F0F0F0Fu);
        }
        if (lane == 0) {
            #pragma unroll
            for (int k = 0; k < 8; k++) { ws[wid*48 + k] = aLo[k]; ws[wid*48 + 8 + k] = aHi[k]; }
            #pragma unroll
            for (int s2 = 0; s2 < 4; s2++)
                #pragma unroll
                for (int k = 0; k < 8; k++) ws[wid*48 + 16 + s2*8 + k] = 0;
            int region = (wid == 0) ? (half ? 2 : 1) : (wid == 1) ? 3 : (wid == 2) ? 4 : 0;
            if (region) {
                #pragma unroll
                for (int k = 0; k < 8; k++) ws[wid*48 + 16 + (region-1)*8 + k] = aB[k];
            }
        }
        __syncthreads();

        if (tid < 8) {
            int k = tid;
            unsigned vlo = 0, vhi = 0;
            #pragma unroll
            for (int wp = 0; wp < NW; wp++) { vlo += ws[wp*48 + k]; vhi += ws[wp*48 + 8 + k]; }
            atomicAdd(&stats[(c4*4 + 0)*8 + k], (int)(vlo & 0xffffu));
            atomicAdd(&stats[(c4*4 + 2)*8 + k], (int)(vlo >> 16));
            atomicAdd(&stats[(c4*4 + 1)*8 + k], (int)(vhi & 0xffffu));
            atomicAdd(&stats[(c4*4 + 3)*8 + k], (int)(vhi >> 16));
        } else if (tid < 40) {
            int t2 = tid - 8;
            int sidx = 1 + (t2 >> 3), k = t2 & 7;
            unsigned v = 0;
            #pragma unroll
            for (int wp = 0; wp < NW; wp++) v += ws[wp*48 + 8 + sidx*8 + k];
            #pragma unroll
            for (int j = 0; j < 4; j++)
                atomicAdd(&stats[sidx*512 + (c4*4 + j)*8 + k], (int)((v >> (8*j)) & 0xffu));
        }
        if (tid < 128) {
            int corner = tid >> 5, l = tid & 31;
            int j = l >> 3, k = l & 7;
            int v = (int)scCor[tid];
            if (v) atomicAdd(&stats[(5 + corner)*512 + (c4*4 + j)*8 + k], v);
        }
    }
}

// ---------------- conv phase: mma.sync int8 conv + BN (+identity), work-steal ---
template<int PASS>
__device__ __forceinline__ void convPhase(
    const float* __restrict__ gamma, const float* __restrict__ beta,
    const float* __restrict__ mean,  const float* __restrict__ var,
    float* __restrict__ dstp, float sp1, float sx,
    unsigned* dynS, float* sAc, float* sBc, float* sF, int* sTile)
{
    const unsigned* __restrict__ inP = (PASS == 1) ? g_qxp : g_q1p;
    const unsigned* __restrict__ wP  = (PASS == 1) ? g_qw1p : g_qw2p;
    unsigned* ctr = &g_ctr[(PASS == 1) ? 1 : 3];
    unsigned* sW  = dynS;            // 16*584 = 9344 words (transposed weights)
    unsigned* sIn = dynS + 9344;     // 16*232 = 3712 words
    int tid = threadIdx.x;
    int wid = tid >> 5, lane = tid & 31;
    int gid = lane >> 2, t4 = lane & 3;
    int w0 = wid * 8;

    // stage weights + BN coefficients ONCE per phase
    if (tid < 64) {
        float inv = gamma[tid] / sqrtf(var[tid] + 1e-5f);
        sAc[tid] = sp1 * inv;
        sBc[tid] = beta[tid] - mean[tid]*inv;
    }
    {
        const uint4* wp4 = (const uint4*)wP;
        for (int i4 = tid; i4 < 2304; i4 += NT) {
            int i = i4 << 2;
            int o = i & 63;
            int cp = i >> 6;
            int c4l = cp / 9;
            int pos = cp - c4l*9;
            uint4 v = wp4[i4];
            unsigned base = c4l*584 + pos*64 + (o >> 3);
            int og = o & 7;
            sW[base + (og + 0)*8] = v.x;
            sW[base + (og + 1)*8] = v.y;
            sW[base + (og + 2)*8] = v.z;
            sW[base + (og + 3)*8] = v.w;
        }
    }

    for (;;) {
        __syncthreads();
        if (tid == 0) *sTile = (int)atomicAdd(ctr, 1u);
        __syncthreads();
        int tile = *sTile;
        if (tile >= 448) break;
        int n  = tile / 28;
        int h0 = (tile - n*28) * 2;

        for (int p = tid; p < 3712; p += NT) {
            int c4r = p / 58;
            int cc  = p - c4r*58;
            int rr  = c4r & 3;
            int c4l = c4r >> 2;
            int gr = h0 - 1 + rr, gc = cc - 1;
            unsigned v = 0;
            if ((unsigned)gr < 56u && (unsigned)gc < 56u)
                v = inP[(n*16 + c4l)*HW + gr*WID + gc];
            sIn[c4l*232 + rr*58 + cc] = v;
        }
        __syncthreads();

        int acc[8][4];
        #pragma unroll
        for (int nt = 0; nt < 8; nt++)
            #pragma unroll
            for (int r = 0; r < 4; r++) acc[nt][r] = 0;

        #pragma unroll
        for (int cg = 0; cg < 2; cg++) {
            int cb = cg * 8;
            #pragma unroll
            for (int ph = 0; ph < 3; ph++) {
                #pragma unroll
                for (int pw = 0; pw < 3; pw++) {
                    int pos = ph*3 + pw;
                    int ccol = w0 + gid + pw;
                    unsigned a0 = sIn[(cb + t4    )*232 +  ph   *58 + ccol];
                    unsigned a1 = sIn[(cb + t4    )*232 + (ph+1)*58 + ccol];
                    unsigned a2 = sIn[(cb + 4 + t4)*232 +  ph   *58 + ccol];
                    unsigned a3 = sIn[(cb + 4 + t4)*232 + (ph+1)*58 + ccol];
                    const uint4* pb0 = (const uint4*)(sW + (cb + t4    )*584 + pos*64 + gid*8);
                    const uint4* pb1 = (const uint4*)(sW + (cb + 4 + t4)*584 + pos*64 + gid*8);
                    uint4 b0lo = pb0[0], b0hi = pb0[1];
                    uint4 b1lo = pb1[0], b1hi = pb1[1];
                    unsigned b0a[8] = {b0lo.x, b0lo.y, b0lo.z, b0lo.w, b0hi.x, b0hi.y, b0hi.z, b0hi.w};
                    unsigned b1a[8] = {b1lo.x, b1lo.y, b1lo.z, b1lo.w, b1hi.x, b1hi.y, b1hi.z, b1hi.w};
                    #pragma unroll
                    for (int nt = 0; nt < 8; nt++)
                        MMA8<PASS>(acc[nt], a0, a1, a2, a3, b0a[nt], b1a[nt]);
                }
            }
        }

        int hw0 = h0*WID + w0 + gid;
        int hw1 = hw0 + WID;
        float mx = 0.f;
        #pragma unroll
        for (int nt = 0; nt < 8; nt++) {
            int o0 = nt*8 + t4*2;
            float A0 = sAc[o0],   B0 = sBc[o0];
            float A1 = sAc[o0+1], B1 = sBc[o0+1];
            float t00 = (float)acc[nt][0] * A0 + B0;
            float t01 = (float)acc[nt][1] * A1 + B1;
            float t10 = (float)acc[nt][2] * A0 + B0;
            float t11 = (float)acc[nt][3] * A1 + B1;
            if (PASS == 2) {
                int c4i = o0 >> 2;
                int sh  = (o0 & 3) * 8;
                unsigned id0 = g_qxp[(n*16 + c4i)*HW + hw0];
                unsigned id1 = g_qxp[(n*16 + c4i)*HW + hw1];
                t00 += (float)((int)(int8_t)((id0 >> sh)     & 0xffu)) * sx;
                t01 += (float)((int)(int8_t)((id0 >> (sh+8)) & 0xffu)) * sx;
                t10 += (float)((int)(int8_t)((id1 >> sh)     & 0xffu)) * sx;
                t11 += (float)((int)(int8_t)((id1 >> (sh+8)) & 0xffu)) * sx;
            }
            dstp[(n*CC + o0    )*HW + hw0] = t00;
            dstp[(n*CC + o0 + 1)*HW + hw0] = t01;
            dstp[(n*CC + o0    )*HW + hw1] = t10;
            dstp[(n*CC + o0 + 1)*HW + hw1] = t11;
            mx = fmaxf(mx, fmaxf(fmaxf(t00, t01), fmaxf(t10, t11)));
        }
        mx = warpMaxPos(mx);
        if (lane == 0) sF[wid] = mx;
        __syncthreads();
        if (tid == 0) {
            float m = sF[0];
            #pragma unroll
            for (int i = 1; i < NW; i++) m = fmaxf(m, sF[i]);
            atomicMaxF((PASS == 1) ? &g_max_r1 : &g_max_r2, m);
        }
    }
}

// ---------------- HM energy from factorized stats ----------------
__device__ __forceinline__ long long energyFor(const int* stats, const int* wsum, int cb) {
    int S   = stats[        cb];
    int r0  = stats[ 512  + cb];
    int r55 = stats[1024  + cb];
    int c0  = stats[1536  + cb];
    int c55 = stats[2048  + cb];
    int s00 = stats[2560  + cb];
    int s0b = stats[3072  + cb];
    int sb0 = stats[3584  + cb];
    int sbb = stats[4096  + cb];
    long long en = 0;
    #pragma unroll
    for (int kh = 0; kh < 3; kh++) {
        #pragma unroll
        for (int kw = 0; kw < 3; kw++) {
            int xs = S;
            if (kh == 2) xs -= r0;  else if (kh == 0) xs -= r55;
            if (kw == 2) xs -= c0;  else if (kw == 0) xs -= c55;
            if (kh == 2 && kw == 2) xs += s00;
            if (kh == 2 && kw == 0) xs += s0b;
            if (kh == 0 && kw == 2) xs += sb0;
            if (kh == 0 && kw == 0) xs += sbb;
            en += (long long)wsum[cb*9 + kh*3 + kw] * (long long)xs;
        }
    }
    return en;
}

// ---------------- the whole pipeline as ONE persistent kernel ----------------
__global__ void __launch_bounds__(NT, 3) megaKernel(
    const float* __restrict__ x,
    const float* __restrict__ w1, const float* __restrict__ w2,
    const float* __restrict__ g1, const float* __restrict__ b1,
    const float* __restrict__ m1, const float* __restrict__ v1,
    const float* __restrict__ g2, const float* __restrict__ b2,
    const float* __restrict__ m2, const float* __restrict__ v2,
    float* __restrict__ out)
{
    __shared__ float sF[NW];
    __shared__ unsigned scCor[128];
    __shared__ unsigned wsArr[NW*48];
    __shared__ int sTile;
    __shared__ float sAc[64], sBc[64];
    __shared__ long long sa[256], se[256];
    extern __shared__ unsigned dynS[];

    int tid = threadIdx.x, b = blockIdx.x;
    int wid = tid >> 5, lane = tid & 31;

    // ================= P0: partial maxes + zeroing =================
    {
        const float4* x4 = (const float4*)x;
        float m = 0.f;
        for (int i = b*NT + tid; i < NN*CC*HW/4; i += GRID*NT) {
            float4 v = x4[i];
            m = fmaxf(m, fmaxf(fmaxf(fabsf(v.x), fabsf(v.y)), fmaxf(fabsf(v.z), fabsf(v.w))));
        }
        m = warpMaxPos(m);
        if (lane == 0) sF[wid] = m;
        __syncthreads();
        if (tid == 0) {
            float mm = sF[0];
            #pragma unroll
            for (int i = 1; i < NW; i++) mm = fmaxf(mm, sF[i]);
            g_partX[b] = mm;
        }
        __syncthreads();
        if (b < 64) {
            const float* w = (b < 32) ? w1 : w2;
            int off = (b & 31) * 1152;
            float mw = 0.f;
            for (int i = tid; i < 1152; i += NT) mw = fmaxf(mw, fabsf(w[off + i]));
            mw = warpMaxPos(mw);
            if (lane == 0) sF[wid] = mw;
            __syncthreads();
            if (tid == 0) {
                float mm = sF[0];
                #pragma unroll
                for (int i = 1; i < NW; i++) mm = fmaxf(mm, sF[i]);
                g_partW[b] = mm;
            }
        }
        if (b == 64) {
            for (int i = tid; i < 4608; i += NT) { g_stats1[i] = 0; g_stats2[i] = 0; }
        }
        if (b == 65 && tid == 0) {
            g_max_r1 = 0.f; g_max_r2 = 0.f;
            g_ctr[0] = 0; g_ctr[1] = 0; g_ctr[2] = 0; g_ctr[3] = 0;
        }
    }
    gridBarrier();

    // ================= P1: final maxes, weight quant+wsum, qs1 =================
    float maxX, maxW1, maxW2;
    {
        float m = 0.f;
        for (int i = tid; i < GRID; i += NT) m = fmaxf(m, g_partX[i]);
        m = warpMaxPos(m);
        if (lane == 0) sF[wid] = m;
        __syncthreads();
        float mm = sF[0];
        #pragma unroll
        for (int i = 1; i < NW; i++) mm = fmaxf(mm, sF[i]);
        maxX = mm;
        float w1m = 0.f, w2m = 0.f;
        #pragma unroll
        for (int i = 0; i < 32; i++) {
            w1m = fmaxf(w1m, g_partW[i]);
            w2m = fmaxf(w2m, g_partW[32 + i]);
        }
        maxW1 = w1m; maxW2 = w2m;
        if (b == 0 && tid == 0) { g_maxabs_x = maxX; g_maxw1 = maxW1; g_maxw2 = maxW2; }
    }
    {   // weight quant + pack + wsum (288 warp-items over first 42 blocks)
        int item = b*NW + wid;
        if (item < 288) {
            const unsigned M = 0x01010101u;
            int sel = item / 144;
            int g   = item - sel*144;
            int c4  = g / 9, pos = g - c4*9;
            const float* w = sel ? w2 : w1;
            float s = (sel ? maxW2 : maxW1) * (1.0f/127.0f);
            unsigned* wpout = sel ? g_qw2p : g_qw1p;
            unsigned wds[2];
            #pragma unroll
            for (int h = 0; h < 2; h++) {
                int o = lane + 32*h;
                unsigned word = 0;
                #pragma unroll
                for (int j = 0; j < 4; j++) {
                    float q = rintf(w[o*576 + (c4*4 + j)*9 + pos] / s);
                    q = fminf(127.f, fmaxf(-127.f, q));
                    word |= (((unsigned)(int)q) & 0xffu) << (8*j);
                }
                wpout[c4*576 + pos*64 + o] = word;
                wds[h] = word;
            }
            unsigned acc8[8];
            #pragma unroll
            for (int k = 0; k < 8; k++)
                acc8[k] = __reduce_add_sync(0xffffffffu, ((wds[0] >> k) & M) + ((wds[1] >> k) & M));
            int j = lane >> 3, k = lane & 7;
            int* wsum = sel ? g_wsum2 : g_wsum1;
            wsum[((c4*4 + j)*8 + k)*9 + pos] = (int)((acc8[k] >> (8*j)) & 0xffu);
        }
    }
    qsPhase<1>(x, 1.0f / (maxX * (1.0f/127.0f)), scCor, wsArr, &sTile);
    gridBarrier();

    // ================= P2: conv1 =================
    {
        float sp1 = (maxX * (1.f/127.f)) * (maxW1 * (1.f/127.f));
        convPhase<1>(g1, b1, m1, v1, g_t1, sp1, 0.f, dynS, sAc, sBc, sF, &sTile);
    }
    gridBarrier();

    // ================= P3: qs2 =================
    {
        float r1 = g_max_r1;
        qsPhase<2>((const float*)g_t1, 1.0f / (r1 * (1.0f/255.0f)), scCor, wsArr, &sTile);
    }
    gridBarrier();

    // ================= P4: conv2 =================
    {
        float r1 = g_max_r1;
        float sp1 = (r1 * (1.f/255.f)) * (maxW2 * (1.f/127.f));
        float sx  = maxX * (1.f/127.f);
        convPhase<2>(g2, b2, m2, v2, out, sp1, sx, dynS, sAc, sBc, sF, &sTile);
    }
    gridBarrier();

    // ================= P5: final QuantReLU + HM finalize =================
    {
        float s = g_max_r2 * (1.f/255.f);
        float sinv = 1.0f / s;
        float4* o4 = (float4*)out;
        for (int i = b*NT + tid; i < NN*CC*HW/4; i += GRID*NT) {
            float4 v = o4[i];
            v.x = (float)::min(255, __float2int_rn(fmaxf(v.x, 0.f) * sinv)) * s;
            v.y = (float)::min(255, __float2int_rn(fmaxf(v.y, 0.f) * sinv)) * s;
            v.z = (float)::min(255, __float2int_rn(fmaxf(v.z, 0.f) * sinv)) * s;
            v.w = (float)::min(255, __float2int_rn(fmaxf(v.w, 0.f) * sinv)) * s;
            o4[i] = v;
        }
        if (b == 0) {
            long long act = 0, en = 0;
            for (int cb = tid; cb < 512; cb += NT) {
                act += (long long)g_stats1[cb] + (long long)g_stats2[cb];
                en  += energyFor(g_stats1, g_wsum1, cb) + energyFor(g_stats2, g_wsum2, cb);
            }
            sa[tid] = act; se[tid] = en;
            if (tid < 32) { sa[NT + tid] = 0; se[NT + tid] = 0; }
            __syncthreads();
            for (int st = 128; st; st >>= 1) {
                if (tid < st) { sa[tid] += sa[tid + st]; se[tid] += se[tid + st]; }
                __syncthreads();
            }
            if (tid == 0) {
                out[NN*CC*HW    ] = (float)sa[0];   // HM_act
                out[NN*CC*HW + 1] = (float)se[0];   // HM_energy
            }
        }
    }
}

#define CONV_SMEM ((9344 + 3712) * 4)

// ---------------- launch ----------------
extern "C" void kernel_launch(void* const* d_in, const int* in_sizes, int n_in,
                              void* d_out, int out_size) {
    const float* x  = (const float*)d_in[0];
    const float* w1 = (const float*)d_in[1];
    const float* w2 = (const float*)d_in[2];
    const float* g1 = (const float*)d_in[3];
    const float* b1 = (const float*)d_in[4];
    const float* m1 = (const float*)d_in[5];
    const float* v1 = (const float*)d_in[6];
    const float* g2 = (const float*)d_in[7];
    const float* b2 = (const float*)d_in[8];
    const float* m2 = (const float*)d_in[9];
    const float* v2 = (const float*)d_in[10];
    float* out = (float*)d_out;

    cudaFuncSetAttribute(megaKernel, cudaFuncAttributeMaxDynamicSharedMemorySize, CONV_SMEM);
    megaKernel<<<GRID, NT, CONV_SMEM>>>(x, w1, w2, g1, b1, m1, v1, g2, b2, m2, v2, out);
}